// round 16
// baseline (speedup 1.0000x reference)
#include <cuda_runtime.h>
#include <cuda_bf16.h>
#include <cstdint>
#include <math.h>

// Problem dims (fixed by the dataset)
#define T 4096
#define E 512
#define BK 16

// -------------------- scratch (allocation-free: __device__ globals) ---------
__device__ float    g_h1[(size_t)T * E];
__device__ float    g_h2hi[(size_t)T * E];
__device__ uint32_t g_h2hb[(size_t)T * E / 2];
__device__ uint32_t g_h2lo[(size_t)T * E / 2];
__device__ float    g_uhi[(size_t)T * E];
__device__ uint32_t g_uhb[(size_t)T * E / 2];
__device__ uint32_t g_ulo[(size_t)T * E / 2];
__device__ float    g_lg[(size_t)T * T];
__device__ float    g_pmax[32 * T];
__device__ float    g_psum[32 * T];
__device__ float    g_cmax[T];
__device__ float    g_csum[T];

// -------------------- helpers ----------------------------------------------
__device__ __forceinline__ uint32_t smem_u32(const void* p) {
    uint32_t a;
    asm("{ .reg .u64 t; cvta.to.shared.u64 t, %1; cvt.u32.u64 %0, t; }"
        : "=r"(a) : "l"(p));
    return a;
}
__device__ __forceinline__ void cp_async16(uint32_t dst, const void* src) {
    asm volatile("cp.async.cg.shared.global [%0], [%1], 16;"
                 :: "r"(dst), "l"(src) : "memory");
}
#define CP_COMMIT() asm volatile("cp.async.commit_group;" ::: "memory")
#define CP_WAIT(N)  asm volatile("cp.async.wait_group %0;" :: "n"(N) : "memory")

__device__ __forceinline__ float tf32f(float x) {
    uint32_t h;
    asm("cvt.rna.tf32.f32 %0, %1;" : "=r"(h) : "f"(x));
    return __uint_as_float(h);
}
__device__ __forceinline__ uint32_t cvt_tf32(float x) {
    uint32_t h;
    asm("cvt.rna.tf32.f32 %0, %1;" : "=r"(h) : "f"(x));
    return h;
}
__device__ __forceinline__ uint32_t pack_bf16x2(float e1, float e0) {
    uint32_t d;
    asm("cvt.rn.bf16x2.f32 %0, %1, %2;" : "=r"(d) : "f"(e1), "f"(e0));
    return d;
}
// inverse fragment permutation: element/pair p -> stored position
__device__ __forceinline__ int mperm(int p) { return ((p & 3) << 1) | (p >> 2); }

__device__ __forceinline__ void mma_tf32_k8(float* c, const uint32_t* a,
                                            const uint32_t* b) {
    asm volatile(
        "mma.sync.aligned.m16n8k8.row.col.f32.tf32.tf32.f32 "
        "{%0,%1,%2,%3}, {%4,%5,%6,%7}, {%8,%9}, {%0,%1,%2,%3};"
        : "+f"(c[0]), "+f"(c[1]), "+f"(c[2]), "+f"(c[3])
        : "r"(a[0]), "r"(a[1]), "r"(a[2]), "r"(a[3]), "r"(b[0]), "r"(b[1]));
}
__device__ __forceinline__ void mma_bf16_k16(float* c, const uint32_t* a,
                                             const uint32_t* b) {
    asm volatile(
        "mma.sync.aligned.m16n8k16.row.col.f32.bf16.bf16.f32 "
        "{%0,%1,%2,%3}, {%4,%5,%6,%7}, {%8,%9}, {%0,%1,%2,%3};"
        : "+f"(c[0]), "+f"(c[1]), "+f"(c[2]), "+f"(c[3])
        : "r"(a[0]), "r"(a[1]), "r"(a[2]), "r"(a[3]), "r"(b[0]), "r"(b[1]));
}

// build hi-bf16x2 and lo-bf16x2 from a float2 (consecutive k)
__device__ __forceinline__ void split_bf(const float2 f, uint32_t& H, uint32_t& L) {
    H = pack_bf16x2(f.y, f.x);
    float lx = f.x - __uint_as_float(cvt_tf32(f.x));
    float ly = f.y - __uint_as_float(cvt_tf32(f.y));
    L = pack_bf16x2(ly, lx);
}

// h2 split emission (z=1 of gemm12 epilogue)
__device__ __forceinline__ void emit_h2(int row, int c, float2 v) {
    float hx = tf32f(v.x), hy = tf32f(v.y);
    int p0 = c & 7;
    int p1 = (c + 1) & 7;
    g_h2hi[(size_t)row * E + (c & ~7) + mperm(p0)] = hx;
    g_h2hi[(size_t)row * E + ((c + 1) & ~7) + mperm(p1)] = hy;
    int pp = c >> 1, q = pp & 7;
    int posp = (pp & ~7) + mperm(q);
    g_h2hb[(size_t)row * (E / 2) + posp] = pack_bf16x2(v.y, v.x);
    g_h2lo[(size_t)row * (E / 2) + posp] = pack_bf16x2(v.y - hy, v.x - hx);
}

// ==================== gemm12: in-loop split hybrid GEMM =====================
#define BM12 128
#define BN12 128
#define APAD12 4
#define ASTR12 (BK + APAD12)              // 20 floats per row
#define STAGE12 (2 * BM12 * ASTR12)
#define NST12 3
#define SMEM12 (NST12 * STAGE12 * 4)      // 61440 B

__global__ __launch_bounds__(256, 2) void gemm12_inloop(
    const float* __restrict__ A0, const float* __restrict__ B0,
    const float* __restrict__ bias0, float* __restrict__ C0, int emit0,
    const float* __restrict__ A1, const float* __restrict__ B1,
    const float* __restrict__ bias1, float* __restrict__ C1, int emit1,
    int M, int N, int K) {
    extern __shared__ float dsm[];

    const float* A = A0;
    const float* B = B0;
    const float* bias = bias0;
    float* C = C0;
    int emit = emit0;
    if (blockIdx.z == 1) { A = A1; B = B1; bias = bias1; C = C1; emit = emit1; }

    const int tid = threadIdx.x;
    const int wid = tid >> 5;
    const int lane = tid & 31;
    const int m0 = blockIdx.y * BM12;
    const int n0 = blockIdx.x * BN12;

    const int wm = (wid >> 2) * 64;
    const int wn = (wid & 3) * 32;
    const int qr = lane >> 2;
    const int qc = lane & 3;

    float acc[4][4][4];
#pragma unroll
    for (int i = 0; i < 4; i++)
#pragma unroll
        for (int j = 0; j < 4; j++)
#pragma unroll
            for (int v = 0; v < 4; v++) acc[i][j][v] = 0.f;

    const float* Abase = A + (size_t)m0 * K;
    const float* Bbase = B + (size_t)n0 * K;

    const int lrow = tid >> 2;
    const int lq = tid & 3;

    const int NC = K / BK;

    auto issue = [&](int c) {
        const int k0 = c * BK;
        float* st = dsm + (c % NST12) * STAGE12;
        float* stB = st + BM12 * ASTR12;
#pragma unroll
        for (int h = 0; h < 2; h++) {
            int row = lrow + h * 64;
            cp_async16(smem_u32(st + (size_t)row * ASTR12 + lq * 4),
                       Abase + (size_t)row * K + k0 + lq * 4);
            cp_async16(smem_u32(stB + (size_t)row * ASTR12 + lq * 4),
                       Bbase + (size_t)row * K + k0 + lq * 4);
        }
        CP_COMMIT();
    };

    issue(0);
    if (NC > 1) issue(1);

    for (int c = 0; c < NC; c++) {
        if (c < NC - 1) { CP_WAIT(1); } else { CP_WAIT(0); }
        __syncthreads();

        const float* st = dsm + (c % NST12) * STAGE12;
        const float* stB = st + BM12 * ASTR12;

        // ---- tf32 hi*hi over two k8 slices --------------------------------
#pragma unroll
        for (int ks = 0; ks < BK; ks += 8) {
            uint32_t ahi[4][4];
#pragma unroll
            for (int mt = 0; mt < 4; mt++) {
                const int mr = wm + mt * 16;
                ahi[mt][0] = cvt_tf32(st[(size_t)(mr + qr) * ASTR12 + ks + qc]);
                ahi[mt][1] = cvt_tf32(st[(size_t)(mr + qr + 8) * ASTR12 + ks + qc]);
                ahi[mt][2] = cvt_tf32(st[(size_t)(mr + qr) * ASTR12 + ks + qc + 4]);
                ahi[mt][3] = cvt_tf32(st[(size_t)(mr + qr + 8) * ASTR12 + ks + qc + 4]);
            }
            uint32_t bhi[4][2];
#pragma unroll
            for (int nt = 0; nt < 4; nt++) {
                const int nr = wn + nt * 8;
                bhi[nt][0] = cvt_tf32(stB[(size_t)(nr + qr) * ASTR12 + ks + qc]);
                bhi[nt][1] = cvt_tf32(stB[(size_t)(nr + qr) * ASTR12 + ks + qc + 4]);
            }
#pragma unroll
            for (int mt = 0; mt < 4; mt++)
#pragma unroll
                for (int nt = 0; nt < 4; nt++)
                    mma_tf32_k8(acc[mt][nt], ahi[mt], bhi[nt]);
        }

        // ---- bf16 cross terms over one k16 slice --------------------------
        uint32_t bH[4][2], bL[4][2];
#pragma unroll
        for (int nt = 0; nt < 4; nt++) {
            const int nr = wn + nt * 8;
            float2 g0 = *(const float2*)&stB[(size_t)(nr + qr) * ASTR12 + 2 * qc];
            float2 g1 = *(const float2*)&stB[(size_t)(nr + qr) * ASTR12 + 2 * qc + 8];
            split_bf(g0, bH[nt][0], bL[nt][0]);
            split_bf(g1, bH[nt][1], bL[nt][1]);
        }
#pragma unroll
        for (int mt = 0; mt < 4; mt++) {
            const int mr = wm + mt * 16;
            float2 f0 = *(const float2*)&st[(size_t)(mr + qr) * ASTR12 + 2 * qc];
            float2 f1 = *(const float2*)&st[(size_t)(mr + qr + 8) * ASTR12 + 2 * qc];
            float2 f2 = *(const float2*)&st[(size_t)(mr + qr) * ASTR12 + 2 * qc + 8];
            float2 f3 = *(const float2*)&st[(size_t)(mr + qr + 8) * ASTR12 + 2 * qc + 8];
            uint32_t aH[4], aL[4];
            split_bf(f0, aH[0], aL[0]);
            split_bf(f1, aH[1], aL[1]);
            split_bf(f2, aH[2], aL[2]);
            split_bf(f3, aH[3], aL[3]);
#pragma unroll
            for (int nt = 0; nt < 4; nt++)
                mma_bf16_k16(acc[mt][nt], aH, bL[nt]);
#pragma unroll
            for (int nt = 0; nt < 4; nt++)
                mma_bf16_k16(acc[mt][nt], aL, bH[nt]);
        }

        if (c + 2 < NC) issue(c + 2);
    }

    // ---- epilogue ----------------------------------------------------------
#pragma unroll
    for (int mt = 0; mt < 4; mt++) {
#pragma unroll
        for (int nt = 0; nt < 4; nt++) {
            const int mrow = m0 + wm + mt * 16 + qr;
            const int ncol = n0 + wn + nt * 8 + qc * 2;
            float bx = bias[ncol], by = bias[ncol + 1];
            float2 v0 = make_float2(acc[mt][nt][0] + bx, acc[mt][nt][1] + by);
            float2 v1 = make_float2(acc[mt][nt][2] + bx, acc[mt][nt][3] + by);
            if (emit) {
                emit_h2(mrow, ncol, v0);
                emit_h2(mrow + 8, ncol, v1);
            } else {
                *(float2*)(C + (size_t)mrow * N + ncol) = v0;
                *(float2*)(C + (size_t)(mrow + 8) * N + ncol) = v1;
            }
        }
    }
}

// ==================== gemm3: pre-split GEMM + fused column stats ============
#define BM3 128
#define BN3 128
#define AHIo 0
#define BHIo (128 * 24)
#define AHBo (2 * 128 * 24)
#define BHBo (AHBo + 128 * 8)
#define ALOo (BHBo + 128 * 8)
#define BLOo (ALOo + 128 * 8)
#define STAGE3 (BLOo + 128 * 8)            // 10240 floats = 40KB
#define SMEM3 (2 * STAGE3 * 4)             // 81920 B

__global__ __launch_bounds__(256, 2) void gemm3_split(
    const float* __restrict__ Ahi, const uint32_t* __restrict__ Ahb,
    const uint32_t* __restrict__ Alo, const float* __restrict__ Bhi,
    const uint32_t* __restrict__ Bhb, const uint32_t* __restrict__ Blo,
    float* __restrict__ C, int N, int K, const float* __restrict__ addmat) {
    extern __shared__ float dsm[];

    const int tid = threadIdx.x;
    const int wid = tid >> 5;
    const int lane = tid & 31;
    const int m0 = blockIdx.y * BM3;
    const int n0 = blockIdx.x * BN3;
    const int wm = (wid >> 2) * 64;
    const int wn = (wid & 3) * 32;
    const int qr = lane >> 2;
    const int qc = lane & 3;
    const int Kh = K >> 1;

    float acc[4][4][4];
#pragma unroll
    for (int i = 0; i < 4; i++)
#pragma unroll
        for (int j = 0; j < 4; j++)
#pragma unroll
            for (int v = 0; v < 4; v++) acc[i][j][v] = 0.f;

    const int NC = K / BK;

    auto issue = [&](int c) {
        const int k0 = c * BK;
        float* st = dsm + (c & 1) * STAGE3;
#pragma unroll
        for (int i = 0; i < 2; i++) {
            int idx = tid + i * 256;
            int row = idx >> 2, u = idx & 3;
            cp_async16(smem_u32(st + AHIo + row * 24 + u * 4),
                       Ahi + (size_t)(m0 + row) * K + k0 + u * 4);
            cp_async16(smem_u32(st + BHIo + row * 24 + u * 4),
                       Bhi + (size_t)(n0 + row) * K + k0 + u * 4);
        }
        {
            int row = tid >> 1, u = tid & 1;
            uint32_t* sb = (uint32_t*)st;
            cp_async16(smem_u32(sb + AHBo + row * 8 + u * 4),
                       Ahb + (size_t)(m0 + row) * Kh + (k0 >> 1) + u * 4);
            cp_async16(smem_u32(sb + BHBo + row * 8 + u * 4),
                       Bhb + (size_t)(n0 + row) * Kh + (k0 >> 1) + u * 4);
            cp_async16(smem_u32(sb + ALOo + row * 8 + u * 4),
                       Alo + (size_t)(m0 + row) * Kh + (k0 >> 1) + u * 4);
            cp_async16(smem_u32(sb + BLOo + row * 8 + u * 4),
                       Blo + (size_t)(n0 + row) * Kh + (k0 >> 1) + u * 4);
        }
        CP_COMMIT();
    };

    issue(0);

    for (int c = 0; c < NC; c++) {
        if (c + 1 < NC) { issue(c + 1); CP_WAIT(1); }
        else            { CP_WAIT(0); }
        __syncthreads();

        const float* base = dsm + (c & 1) * STAGE3;
        const float* sAhi = base + AHIo;
        const float* sBhi = base + BHIo;
        const uint32_t* sAhb = (const uint32_t*)base + AHBo;
        const uint32_t* sBhb = (const uint32_t*)base + BHBo;
        const uint32_t* sAlo = (const uint32_t*)base + ALOo;
        const uint32_t* sBlo = (const uint32_t*)base + BLOo;

        // ---- tf32 hi*hi: two k8 slices ------------------------------------
#pragma unroll
        for (int s5 = 0; s5 < 2; s5++) {
            uint32_t af[4][4];
#pragma unroll
            for (int mt = 0; mt < 4; mt++) {
                const float* p = sAhi + (size_t)(wm + mt * 16 + qr) * 24 + s5 * 8 + 2 * qc;
                uint2 x0 = *(const uint2*)p;
                uint2 x1v = *(const uint2*)(p + 8 * 24);
                af[mt][0] = x0.x; af[mt][1] = x1v.x;
                af[mt][2] = x0.y; af[mt][3] = x1v.y;
            }
            uint32_t bfr[4][2];
#pragma unroll
            for (int nt = 0; nt < 4; nt++) {
                const float* p = sBhi + (size_t)(wn + nt * 8 + qr) * 24 + s5 * 8 + 2 * qc;
                uint2 y = *(const uint2*)p;
                bfr[nt][0] = y.x; bfr[nt][1] = y.y;
            }
#pragma unroll
            for (int mt = 0; mt < 4; mt++)
#pragma unroll
                for (int nt = 0; nt < 4; nt++)
                    mma_tf32_k8(acc[mt][nt], af[mt], bfr[nt]);
        }

        // ---- bf16 cross terms: one k16 slice ------------------------------
        uint32_t bH[4][2], bL[4][2];
#pragma unroll
        for (int nt = 0; nt < 4; nt++) {
            size_t off = (size_t)(wn + nt * 8 + qr) * 8 + 2 * qc;
            uint2 h = *(const uint2*)(sBhb + off);
            uint2 l = *(const uint2*)(sBlo + off);
            bH[nt][0] = h.x; bH[nt][1] = h.y;
            bL[nt][0] = l.x; bL[nt][1] = l.y;
        }
#pragma unroll
        for (int mt = 0; mt < 4; mt++) {
            size_t off = (size_t)(wm + mt * 16 + qr) * 8 + 2 * qc;
            uint2 h0 = *(const uint2*)(sAhb + off);
            uint2 h1 = *(const uint2*)(sAhb + off + 64);
            uint2 l0 = *(const uint2*)(sAlo + off);
            uint2 l1 = *(const uint2*)(sAlo + off + 64);
            uint32_t aH[4] = {h0.x, h1.x, h0.y, h1.y};
            uint32_t aL[4] = {l0.x, l1.x, l0.y, l1.y};
#pragma unroll
            for (int nt = 0; nt < 4; nt++)
                mma_bf16_k16(acc[mt][nt], aH, bL[nt]);
#pragma unroll
            for (int nt = 0; nt < 4; nt++)
                mma_bf16_k16(acc[mt][nt], aL, bH[nt]);
        }
        __syncthreads();
    }

    // ---- epilogue: write lg + fused per-column (max, sumexp) partials ------
    float cm[4][2], cs[4][2];
#pragma unroll
    for (int nt = 0; nt < 4; nt++) {
        cm[nt][0] = -1e30f; cm[nt][1] = -1e30f;
        cs[nt][0] = 0.f;    cs[nt][1] = 0.f;
    }

    // pass 1: finalize values in-place, write lg, track column max
#pragma unroll
    for (int mt = 0; mt < 4; mt++) {
#pragma unroll
        for (int nt = 0; nt < 4; nt++) {
            const int mrow = m0 + wm + mt * 16 + qr;
            const int ncol = n0 + wn + nt * 8 + qc * 2;
            float2 g0 = *(const float2*)(addmat + (size_t)mrow * N + ncol);
            float2 g1 = *(const float2*)(addmat + (size_t)(mrow + 8) * N + ncol);
            float2 v0 = make_float2(acc[mt][nt][0] + g0.x, acc[mt][nt][1] + g0.y);
            float2 v1 = make_float2(acc[mt][nt][2] + g1.x, acc[mt][nt][3] + g1.y);
            *(float2*)(C + (size_t)mrow * N + ncol) = v0;
            *(float2*)(C + (size_t)(mrow + 8) * N + ncol) = v1;
            acc[mt][nt][0] = v0.x; acc[mt][nt][1] = v0.y;
            acc[mt][nt][2] = v1.x; acc[mt][nt][3] = v1.y;
            cm[nt][0] = fmaxf(cm[nt][0], fmaxf(v0.x, v1.x));
            cm[nt][1] = fmaxf(cm[nt][1], fmaxf(v0.y, v1.y));
        }
    }
    // pass 2: sum-exp relative to thread-local column max
#pragma unroll
    for (int mt = 0; mt < 4; mt++)
#pragma unroll
        for (int nt = 0; nt < 4; nt++) {
            cs[nt][0] += expf(acc[mt][nt][0] - cm[nt][0]) +
                         expf(acc[mt][nt][2] - cm[nt][0]);
            cs[nt][1] += expf(acc[mt][nt][1] - cm[nt][1]) +
                         expf(acc[mt][nt][3] - cm[nt][1]);
        }
    // butterfly merge across the 8 lanes sharing each column (stride 4,8,16)
#pragma unroll
    for (int s = 4; s <= 16; s <<= 1) {
#pragma unroll
        for (int nt = 0; nt < 4; nt++)
#pragma unroll
            for (int p = 0; p < 2; p++) {
                float om = __shfl_xor_sync(0xffffffffu, cm[nt][p], s);
                float os = __shfl_xor_sync(0xffffffffu, cs[nt][p], s);
                float nm = fmaxf(cm[nt][p], om);
                cs[nt][p] = cs[nt][p] * expf(cm[nt][p] - nm) + os * expf(om - nm);
                cm[nt][p] = nm;
            }
    }
    // cross-warp merge via smem (warp w covers rows wm..wm+63; pair (w, w+4))
    float* smax = dsm;          // 8 warps x 32 cols
    float* ssum = dsm + 256;
    if (lane < 4) {
#pragma unroll
        for (int nt = 0; nt < 4; nt++)
#pragma unroll
            for (int p = 0; p < 2; p++) {
                int lc = nt * 8 + lane * 2 + p;
                smax[wid * 32 + lc] = cm[nt][p];
                ssum[wid * 32 + lc] = cs[nt][p];
            }
    }
    __syncthreads();
    if (tid < 128) {
        int w = tid >> 5, lc = tid & 31;
        float m1 = smax[w * 32 + lc],      s1 = ssum[w * 32 + lc];
        float m2 = smax[(w + 4) * 32 + lc], s2 = ssum[(w + 4) * 32 + lc];
        float nm = fmaxf(m1, m2);
        float ns = s1 * expf(m1 - nm) + s2 * expf(m2 - nm);
        int col = n0 + w * 32 + lc;
        g_pmax[blockIdx.y * T + col] = nm;
        g_psum[blockIdx.y * T + col] = ns;
    }
}

// -------------------- band row-sum of h1 -> u splits ------------------------
#define WR 128
#define WC 32
#define HALO 63

__global__ __launch_bounds__(256) void bandsum_kernel(const float* __restrict__ h) {
    __shared__ float s[WR + 2 * HALO][WC];

    const int r0 = blockIdx.y * WR;
    const int c0 = blockIdx.x * WC;
    const int tid = threadIdx.x;
    const int col = tid & 31;

    for (int rr = tid >> 5; rr < WR + 2 * HALO; rr += 8) {
        int gr = r0 - HALO + rr;
        float v = 0.f;
        if (gr >= 0 && gr < T) v = h[(size_t)gr * E + c0 + col];
        s[rr][col] = v;
    }
    __syncthreads();

    const int strip = tid >> 5;
    const int i0 = strip * 16;

    float w0 = 0.f, w1 = 0.f, w2 = 0.f, w3 = 0.f;
#pragma unroll 8
    for (int t = 0; t < 124; t += 4) {
        w0 += s[i0 + t + 0][col];
        w1 += s[i0 + t + 1][col];
        w2 += s[i0 + t + 2][col];
        w3 += s[i0 + t + 3][col];
    }
    w0 += s[i0 + 124][col];
    w1 += s[i0 + 125][col];
    w2 += s[i0 + 126][col];
    float w = (w0 + w1) + (w2 + w3);

    const int c = c0 + col;
    const int pos = (c & ~7) + mperm(c & 7);
    const int pp = c >> 1, q = pp & 7;
    const int posp = (pp & ~7) + mperm(q);

#pragma unroll
    for (int t = 0; t < 16; t++) {
        int gi = r0 + i0 + t;
        float wp = __shfl_xor_sync(0xffffffffu, w, 1);
        float hw = tf32f(w);
        g_uhi[(size_t)gi * E + pos] = hw;
        if (!(col & 1)) {
            float hp = tf32f(wp);
            g_uhb[(size_t)gi * (E / 2) + posp] = pack_bf16x2(wp, w);
            g_ulo[(size_t)gi * (E / 2) + posp] = pack_bf16x2(wp - hp, w - hw);
        }
        if (t < 15) w += s[i0 + t + 127][col] - s[i0 + t][col];
    }
}

// -------------------- merge 32 per-block partials per column ----------------
__global__ __launch_bounds__(256) void colmerge(const float* __restrict__ pmax,
                                                const float* __restrict__ psum,
                                                float* __restrict__ cmax,
                                                float* __restrict__ csum) {
    int col = blockIdx.x * 256 + threadIdx.x;
    float m = -1e30f, s = 0.f;
#pragma unroll 8
    for (int b = 0; b < 32; b++) {
        float bm = pmax[b * T + col];
        float bs = psum[b * T + col];
        float nm = fmaxf(m, bm);
        s = s * expf(m - nm) + bs * expf(bm - nm);
        m = nm;
    }
    cmax[col] = m;
    csum[col] = s;
}

// -------------------- finalize: out = exp(lg - max_col) / sum_col -----------
__global__ __launch_bounds__(256) void finalize_kernel(const float* __restrict__ lg,
                                                       const float* __restrict__ cmax,
                                                       const float* __restrict__ csum,
                                                       float* __restrict__ out) {
    size_t i = (size_t)blockIdx.x * blockDim.x + threadIdx.x;
    size_t base = i * 4;
    int c = (int)(base & (T - 1));
    float4 v = *(const float4*)(lg + base);
    float4 M = *(const float4*)(cmax + c);
    float4 S = *(const float4*)(csum + c);
    float4 o;
    o.x = expf(v.x - M.x) / S.x;
    o.y = expf(v.y - M.y) / S.y;
    o.z = expf(v.z - M.z) / S.z;
    o.w = expf(v.w - M.w) / S.w;
    *(float4*)(out + base) = o;
}

// -------------------- no-op: keeps gemm3 in ncu's captured slot (idx 3) -----
__global__ void dummy_kernel() {}

// -------------------- launch ------------------------------------------------
extern "C" void kernel_launch(void* const* d_in, const int* in_sizes, int n_in,
                              void* d_out, int out_size) {
    const float* x1 = (const float*)d_in[0];   // (T, T)
    const float* x2 = (const float*)d_in[1];   // (T, T)
    const float* W1 = (const float*)d_in[2];   // (E, T)
    const float* b1 = (const float*)d_in[3];   // (E,)
    const float* W2 = (const float*)d_in[4];   // (E, T)
    const float* b2 = (const float*)d_in[5];   // (E,)
    const float* ga = (const float*)d_in[6];   // (T, T)
    float* out = (float*)d_out;

    float *h1, *h2hi, *uhi, *lg, *pmax, *psum, *cmax, *csum;
    uint32_t *h2hb, *h2lo, *uhb, *ulo;
    cudaGetSymbolAddress((void**)&h1, g_h1);
    cudaGetSymbolAddress((void**)&h2hi, g_h2hi);
    cudaGetSymbolAddress((void**)&h2hb, g_h2hb);
    cudaGetSymbolAddress((void**)&h2lo, g_h2lo);
    cudaGetSymbolAddress((void**)&uhi, g_uhi);
    cudaGetSymbolAddress((void**)&uhb, g_uhb);
    cudaGetSymbolAddress((void**)&ulo, g_ulo);
    cudaGetSymbolAddress((void**)&lg, g_lg);
    cudaGetSymbolAddress((void**)&pmax, g_pmax);
    cudaGetSymbolAddress((void**)&psum, g_psum);
    cudaGetSymbolAddress((void**)&cmax, g_cmax);
    cudaGetSymbolAddress((void**)&csum, g_csum);

    cudaFuncSetAttribute(gemm12_inloop, cudaFuncAttributeMaxDynamicSharedMemorySize,
                         SMEM12);
    cudaFuncSetAttribute(gemm3_split, cudaFuncAttributeMaxDynamicSharedMemorySize,
                         SMEM3);

    // 0: z=0 -> h1 = x1@W1^T+b1 (raw); z=1 -> h2 = x2@W2^T+b2 (emit splits)
    gemm12_inloop<<<dim3(E / BN12, T / BM12, 2), 256, SMEM12>>>(
        x1, W1, b1, h1, 0,
        x2, W2, b2, nullptr, 1,
        T, E, T);
    // 1: u = bandsum(h1), emitted as splits
    bandsum_kernel<<<dim3(E / WC, T / WR), 256>>>(h1);
    // 2: no-op (keeps gemm3 at ncu capture index 3)
    dummy_kernel<<<1, 32>>>();
    // 3: lg = u @ h2^T + global_att, fused column-stat partials
    gemm3_split<<<dim3(T / BN3, T / BM3), 256, SMEM3>>>(
        uhi, uhb, ulo, h2hi, h2hb, h2lo, lg, T, E, ga);
    // 4: merge partials -> global column stats
    colmerge<<<T / 256, 256>>>(pmax, psum, cmax, csum);
    // 5: out = exp(lg - max)/sum
    finalize_kernel<<<((size_t)T * T / 4) / 256, 256>>>(lg, cmax, csum, out);
}

// round 17
// speedup vs baseline: 1.5915x; 1.5915x over previous
#include <cuda_runtime.h>
#include <cuda_bf16.h>
#include <cstdint>
#include <math.h>

// Problem dims (fixed by the dataset)
#define T 4096
#define E 512
#define BK 16

// -------------------- scratch (allocation-free: __device__ globals) ---------
__device__ float    g_h1[(size_t)T * E];
__device__ float    g_h2hi[(size_t)T * E];
__device__ uint32_t g_h2hb[(size_t)T * E / 2];
__device__ uint32_t g_h2lo[(size_t)T * E / 2];
__device__ float    g_uhi[(size_t)T * E];
__device__ uint32_t g_uhb[(size_t)T * E / 2];
__device__ uint32_t g_ulo[(size_t)T * E / 2];
__device__ float    g_lg[(size_t)T * T];
__device__ float    g_cmax[T];
__device__ float    g_csum[T];

// -------------------- helpers ----------------------------------------------
__device__ __forceinline__ uint32_t smem_u32(const void* p) {
    uint32_t a;
    asm("{ .reg .u64 t; cvta.to.shared.u64 t, %1; cvt.u32.u64 %0, t; }"
        : "=r"(a) : "l"(p));
    return a;
}
__device__ __forceinline__ void cp_async16(uint32_t dst, const void* src) {
    asm volatile("cp.async.cg.shared.global [%0], [%1], 16;"
                 :: "r"(dst), "l"(src) : "memory");
}
#define CP_COMMIT() asm volatile("cp.async.commit_group;" ::: "memory")
#define CP_WAIT(N)  asm volatile("cp.async.wait_group %0;" :: "n"(N) : "memory")

__device__ __forceinline__ float tf32f(float x) {
    uint32_t h;
    asm("cvt.rna.tf32.f32 %0, %1;" : "=r"(h) : "f"(x));
    return __uint_as_float(h);
}
__device__ __forceinline__ uint32_t cvt_tf32(float x) {
    uint32_t h;
    asm("cvt.rna.tf32.f32 %0, %1;" : "=r"(h) : "f"(x));
    return h;
}
__device__ __forceinline__ uint32_t pack_bf16x2(float e1, float e0) {
    uint32_t d;
    asm("cvt.rn.bf16x2.f32 %0, %1, %2;" : "=r"(d) : "f"(e1), "f"(e0));
    return d;
}
// inverse fragment permutation: element/pair p -> stored position
__device__ __forceinline__ int mperm(int p) { return ((p & 3) << 1) | (p >> 2); }

__device__ __forceinline__ void mma_tf32_k8(float* c, const uint32_t* a,
                                            const uint32_t* b) {
    asm volatile(
        "mma.sync.aligned.m16n8k8.row.col.f32.tf32.tf32.f32 "
        "{%0,%1,%2,%3}, {%4,%5,%6,%7}, {%8,%9}, {%0,%1,%2,%3};"
        : "+f"(c[0]), "+f"(c[1]), "+f"(c[2]), "+f"(c[3])
        : "r"(a[0]), "r"(a[1]), "r"(a[2]), "r"(a[3]), "r"(b[0]), "r"(b[1]));
}
__device__ __forceinline__ void mma_bf16_k16(float* c, const uint32_t* a,
                                             const uint32_t* b) {
    asm volatile(
        "mma.sync.aligned.m16n8k16.row.col.f32.bf16.bf16.f32 "
        "{%0,%1,%2,%3}, {%4,%5,%6,%7}, {%8,%9}, {%0,%1,%2,%3};"
        : "+f"(c[0]), "+f"(c[1]), "+f"(c[2]), "+f"(c[3])
        : "r"(a[0]), "r"(a[1]), "r"(a[2]), "r"(a[3]), "r"(b[0]), "r"(b[1]));
}

// build hi-bf16x2 and lo-bf16x2 from a float2 (consecutive k)
__device__ __forceinline__ void split_bf(const float2 f, uint32_t& H, uint32_t& L) {
    H = pack_bf16x2(f.y, f.x);
    float lx = f.x - __uint_as_float(cvt_tf32(f.x));
    float ly = f.y - __uint_as_float(cvt_tf32(f.y));
    L = pack_bf16x2(ly, lx);
}

// h2 split emission (z=1 of gemm12 epilogue)
__device__ __forceinline__ void emit_h2(int row, int c, float2 v) {
    float hx = tf32f(v.x), hy = tf32f(v.y);
    int p0 = c & 7;
    int p1 = (c + 1) & 7;
    g_h2hi[(size_t)row * E + (c & ~7) + mperm(p0)] = hx;
    g_h2hi[(size_t)row * E + ((c + 1) & ~7) + mperm(p1)] = hy;
    int pp = c >> 1, q = pp & 7;
    int posp = (pp & ~7) + mperm(q);
    g_h2hb[(size_t)row * (E / 2) + posp] = pack_bf16x2(v.y, v.x);
    g_h2lo[(size_t)row * (E / 2) + posp] = pack_bf16x2(v.y - hy, v.x - hx);
}

// ==================== gemm12: in-loop split hybrid GEMM =====================
#define BM12 128
#define BN12 128
#define APAD12 4
#define ASTR12 (BK + APAD12)              // 20 floats per row
#define STAGE12 (2 * BM12 * ASTR12)
#define NST12 3
#define SMEM12 (NST12 * STAGE12 * 4)      // 61440 B

__global__ __launch_bounds__(256, 2) void gemm12_inloop(
    const float* __restrict__ A0, const float* __restrict__ B0,
    const float* __restrict__ bias0, float* __restrict__ C0, int emit0,
    const float* __restrict__ A1, const float* __restrict__ B1,
    const float* __restrict__ bias1, float* __restrict__ C1, int emit1,
    int M, int N, int K) {
    extern __shared__ float dsm[];

    const float* A = A0;
    const float* B = B0;
    const float* bias = bias0;
    float* C = C0;
    int emit = emit0;
    if (blockIdx.z == 1) { A = A1; B = B1; bias = bias1; C = C1; emit = emit1; }

    const int tid = threadIdx.x;
    const int wid = tid >> 5;
    const int lane = tid & 31;
    const int m0 = blockIdx.y * BM12;
    const int n0 = blockIdx.x * BN12;

    const int wm = (wid >> 2) * 64;
    const int wn = (wid & 3) * 32;
    const int qr = lane >> 2;
    const int qc = lane & 3;

    float acc[4][4][4];
#pragma unroll
    for (int i = 0; i < 4; i++)
#pragma unroll
        for (int j = 0; j < 4; j++)
#pragma unroll
            for (int v = 0; v < 4; v++) acc[i][j][v] = 0.f;

    const float* Abase = A + (size_t)m0 * K;
    const float* Bbase = B + (size_t)n0 * K;

    const int lrow = tid >> 2;
    const int lq = tid & 3;

    const int NC = K / BK;

    auto issue = [&](int c) {
        const int k0 = c * BK;
        float* st = dsm + (c % NST12) * STAGE12;
        float* stB = st + BM12 * ASTR12;
#pragma unroll
        for (int h = 0; h < 2; h++) {
            int row = lrow + h * 64;
            cp_async16(smem_u32(st + (size_t)row * ASTR12 + lq * 4),
                       Abase + (size_t)row * K + k0 + lq * 4);
            cp_async16(smem_u32(stB + (size_t)row * ASTR12 + lq * 4),
                       Bbase + (size_t)row * K + k0 + lq * 4);
        }
        CP_COMMIT();
    };

    issue(0);
    if (NC > 1) issue(1);

    for (int c = 0; c < NC; c++) {
        if (c < NC - 1) { CP_WAIT(1); } else { CP_WAIT(0); }
        __syncthreads();

        const float* st = dsm + (c % NST12) * STAGE12;
        const float* stB = st + BM12 * ASTR12;

        // ---- tf32 hi*hi over two k8 slices --------------------------------
#pragma unroll
        for (int ks = 0; ks < BK; ks += 8) {
            uint32_t ahi[4][4];
#pragma unroll
            for (int mt = 0; mt < 4; mt++) {
                const int mr = wm + mt * 16;
                ahi[mt][0] = cvt_tf32(st[(size_t)(mr + qr) * ASTR12 + ks + qc]);
                ahi[mt][1] = cvt_tf32(st[(size_t)(mr + qr + 8) * ASTR12 + ks + qc]);
                ahi[mt][2] = cvt_tf32(st[(size_t)(mr + qr) * ASTR12 + ks + qc + 4]);
                ahi[mt][3] = cvt_tf32(st[(size_t)(mr + qr + 8) * ASTR12 + ks + qc + 4]);
            }
            uint32_t bhi[4][2];
#pragma unroll
            for (int nt = 0; nt < 4; nt++) {
                const int nr = wn + nt * 8;
                bhi[nt][0] = cvt_tf32(stB[(size_t)(nr + qr) * ASTR12 + ks + qc]);
                bhi[nt][1] = cvt_tf32(stB[(size_t)(nr + qr) * ASTR12 + ks + qc + 4]);
            }
#pragma unroll
            for (int mt = 0; mt < 4; mt++)
#pragma unroll
                for (int nt = 0; nt < 4; nt++)
                    mma_tf32_k8(acc[mt][nt], ahi[mt], bhi[nt]);
        }

        // ---- bf16 cross terms over one k16 slice --------------------------
        uint32_t bH[4][2], bL[4][2];
#pragma unroll
        for (int nt = 0; nt < 4; nt++) {
            const int nr = wn + nt * 8;
            float2 g0 = *(const float2*)&stB[(size_t)(nr + qr) * ASTR12 + 2 * qc];
            float2 g1 = *(const float2*)&stB[(size_t)(nr + qr) * ASTR12 + 2 * qc + 8];
            split_bf(g0, bH[nt][0], bL[nt][0]);
            split_bf(g1, bH[nt][1], bL[nt][1]);
        }
#pragma unroll
        for (int mt = 0; mt < 4; mt++) {
            const int mr = wm + mt * 16;
            float2 f0 = *(const float2*)&st[(size_t)(mr + qr) * ASTR12 + 2 * qc];
            float2 f1 = *(const float2*)&st[(size_t)(mr + qr + 8) * ASTR12 + 2 * qc];
            float2 f2 = *(const float2*)&st[(size_t)(mr + qr) * ASTR12 + 2 * qc + 8];
            float2 f3 = *(const float2*)&st[(size_t)(mr + qr + 8) * ASTR12 + 2 * qc + 8];
            uint32_t aH[4], aL[4];
            split_bf(f0, aH[0], aL[0]);
            split_bf(f1, aH[1], aL[1]);
            split_bf(f2, aH[2], aL[2]);
            split_bf(f3, aH[3], aL[3]);
#pragma unroll
            for (int nt = 0; nt < 4; nt++)
                mma_bf16_k16(acc[mt][nt], aH, bL[nt]);
#pragma unroll
            for (int nt = 0; nt < 4; nt++)
                mma_bf16_k16(acc[mt][nt], aL, bH[nt]);
        }

        if (c + 2 < NC) issue(c + 2);
    }

    // ---- epilogue ----------------------------------------------------------
#pragma unroll
    for (int mt = 0; mt < 4; mt++) {
#pragma unroll
        for (int nt = 0; nt < 4; nt++) {
            const int mrow = m0 + wm + mt * 16 + qr;
            const int ncol = n0 + wn + nt * 8 + qc * 2;
            float bx = bias[ncol], by = bias[ncol + 1];
            float2 v0 = make_float2(acc[mt][nt][0] + bx, acc[mt][nt][1] + by);
            float2 v1 = make_float2(acc[mt][nt][2] + bx, acc[mt][nt][3] + by);
            if (emit) {
                emit_h2(mrow, ncol, v0);
                emit_h2(mrow + 8, ncol, v1);
            } else {
                *(float2*)(C + (size_t)mrow * N + ncol) = v0;
                *(float2*)(C + (size_t)(mrow + 8) * N + ncol) = v1;
            }
        }
    }
}

// ==================== gemm3: pre-split hybrid GEMM ==========================
#define BM3 128
#define BN3 128
#define AHIo 0
#define BHIo (128 * 24)
#define AHBo (2 * 128 * 24)
#define BHBo (AHBo + 128 * 8)
#define ALOo (BHBo + 128 * 8)
#define BLOo (ALOo + 128 * 8)
#define STAGE3 (BLOo + 128 * 8)            // 10240 floats = 40KB
#define SMEM3 (2 * STAGE3 * 4)             // 81920 B

__global__ __launch_bounds__(256, 2) void gemm3_split(
    const float* __restrict__ Ahi, const uint32_t* __restrict__ Ahb,
    const uint32_t* __restrict__ Alo, const float* __restrict__ Bhi,
    const uint32_t* __restrict__ Bhb, const uint32_t* __restrict__ Blo,
    float* __restrict__ C, int N, int K, const float* __restrict__ addmat) {
    extern __shared__ float dsm[];

    const int tid = threadIdx.x;
    const int wid = tid >> 5;
    const int lane = tid & 31;
    const int m0 = blockIdx.y * BM3;
    const int n0 = blockIdx.x * BN3;
    const int wm = (wid >> 2) * 64;
    const int wn = (wid & 3) * 32;
    const int qr = lane >> 2;
    const int qc = lane & 3;
    const int Kh = K >> 1;

    float acc[4][4][4];
#pragma unroll
    for (int i = 0; i < 4; i++)
#pragma unroll
        for (int j = 0; j < 4; j++)
#pragma unroll
            for (int v = 0; v < 4; v++) acc[i][j][v] = 0.f;

    const int NC = K / BK;

    auto issue = [&](int c) {
        const int k0 = c * BK;
        float* st = dsm + (c & 1) * STAGE3;
#pragma unroll
        for (int i = 0; i < 2; i++) {
            int idx = tid + i * 256;
            int row = idx >> 2, u = idx & 3;
            cp_async16(smem_u32(st + AHIo + row * 24 + u * 4),
                       Ahi + (size_t)(m0 + row) * K + k0 + u * 4);
            cp_async16(smem_u32(st + BHIo + row * 24 + u * 4),
                       Bhi + (size_t)(n0 + row) * K + k0 + u * 4);
        }
        {
            int row = tid >> 1, u = tid & 1;
            uint32_t* sb = (uint32_t*)st;
            cp_async16(smem_u32(sb + AHBo + row * 8 + u * 4),
                       Ahb + (size_t)(m0 + row) * Kh + (k0 >> 1) + u * 4);
            cp_async16(smem_u32(sb + BHBo + row * 8 + u * 4),
                       Bhb + (size_t)(n0 + row) * Kh + (k0 >> 1) + u * 4);
            cp_async16(smem_u32(sb + ALOo + row * 8 + u * 4),
                       Alo + (size_t)(m0 + row) * Kh + (k0 >> 1) + u * 4);
            cp_async16(smem_u32(sb + BLOo + row * 8 + u * 4),
                       Blo + (size_t)(n0 + row) * Kh + (k0 >> 1) + u * 4);
        }
        CP_COMMIT();
    };

    issue(0);

    for (int c = 0; c < NC; c++) {
        if (c + 1 < NC) { issue(c + 1); CP_WAIT(1); }
        else            { CP_WAIT(0); }
        __syncthreads();

        const float* base = dsm + (c & 1) * STAGE3;
        const float* sAhi = base + AHIo;
        const float* sBhi = base + BHIo;
        const uint32_t* sAhb = (const uint32_t*)base + AHBo;
        const uint32_t* sBhb = (const uint32_t*)base + BHBo;
        const uint32_t* sAlo = (const uint32_t*)base + ALOo;
        const uint32_t* sBlo = (const uint32_t*)base + BLOo;

        // ---- tf32 hi*hi: two k8 slices ------------------------------------
#pragma unroll
        for (int s5 = 0; s5 < 2; s5++) {
            uint32_t af[4][4];
#pragma unroll
            for (int mt = 0; mt < 4; mt++) {
                const float* p = sAhi + (size_t)(wm + mt * 16 + qr) * 24 + s5 * 8 + 2 * qc;
                uint2 x0 = *(const uint2*)p;
                uint2 x1v = *(const uint2*)(p + 8 * 24);
                af[mt][0] = x0.x; af[mt][1] = x1v.x;
                af[mt][2] = x0.y; af[mt][3] = x1v.y;
            }
            uint32_t bfr[4][2];
#pragma unroll
            for (int nt = 0; nt < 4; nt++) {
                const float* p = sBhi + (size_t)(wn + nt * 8 + qr) * 24 + s5 * 8 + 2 * qc;
                uint2 y = *(const uint2*)p;
                bfr[nt][0] = y.x; bfr[nt][1] = y.y;
            }
#pragma unroll
            for (int mt = 0; mt < 4; mt++)
#pragma unroll
                for (int nt = 0; nt < 4; nt++)
                    mma_tf32_k8(acc[mt][nt], af[mt], bfr[nt]);
        }

        // ---- bf16 cross terms: one k16 slice ------------------------------
        uint32_t bH[4][2], bL[4][2];
#pragma unroll
        for (int nt = 0; nt < 4; nt++) {
            size_t off = (size_t)(wn + nt * 8 + qr) * 8 + 2 * qc;
            uint2 h = *(const uint2*)(sBhb + off);
            uint2 l = *(const uint2*)(sBlo + off);
            bH[nt][0] = h.x; bH[nt][1] = h.y;
            bL[nt][0] = l.x; bL[nt][1] = l.y;
        }
#pragma unroll
        for (int mt = 0; mt < 4; mt++) {
            size_t off = (size_t)(wm + mt * 16 + qr) * 8 + 2 * qc;
            uint2 h0 = *(const uint2*)(sAhb + off);
            uint2 h1 = *(const uint2*)(sAhb + off + 64);
            uint2 l0 = *(const uint2*)(sAlo + off);
            uint2 l1 = *(const uint2*)(sAlo + off + 64);
            uint32_t aH[4] = {h0.x, h1.x, h0.y, h1.y};
            uint32_t aL[4] = {l0.x, l1.x, l0.y, l1.y};
#pragma unroll
            for (int nt = 0; nt < 4; nt++)
                mma_bf16_k16(acc[mt][nt], aH, bL[nt]);
#pragma unroll
            for (int nt = 0; nt < 4; nt++)
                mma_bf16_k16(acc[mt][nt], aL, bH[nt]);
        }
        __syncthreads();
    }

    // ---- epilogue ----------------------------------------------------------
#pragma unroll
    for (int mt = 0; mt < 4; mt++) {
#pragma unroll
        for (int nt = 0; nt < 4; nt++) {
            const int mrow = m0 + wm + mt * 16 + qr;
            const int ncol = n0 + wn + nt * 8 + qc * 2;
            float2 v0 = make_float2(acc[mt][nt][0], acc[mt][nt][1]);
            float2 v1 = make_float2(acc[mt][nt][2], acc[mt][nt][3]);
            float2 g0 = *(const float2*)(addmat + (size_t)mrow * N + ncol);
            float2 g1 = *(const float2*)(addmat + (size_t)(mrow + 8) * N + ncol);
            v0.x += g0.x; v0.y += g0.y;
            v1.x += g1.x; v1.y += g1.y;
            *(float2*)(C + (size_t)mrow * N + ncol) = v0;
            *(float2*)(C + (size_t)(mrow + 8) * N + ncol) = v1;
        }
    }
}

// -------------------- band row-sum of h1 -> u splits ------------------------
#define WR 128
#define WC 32
#define HALO 63

__global__ __launch_bounds__(256) void bandsum_kernel(const float* __restrict__ h) {
    __shared__ float s[WR + 2 * HALO][WC];

    const int r0 = blockIdx.y * WR;
    const int c0 = blockIdx.x * WC;
    const int tid = threadIdx.x;
    const int col = tid & 31;

    for (int rr = tid >> 5; rr < WR + 2 * HALO; rr += 8) {
        int gr = r0 - HALO + rr;
        float v = 0.f;
        if (gr >= 0 && gr < T) v = h[(size_t)gr * E + c0 + col];
        s[rr][col] = v;
    }
    __syncthreads();

    const int strip = tid >> 5;
    const int i0 = strip * 16;

    float w0 = 0.f, w1 = 0.f, w2 = 0.f, w3 = 0.f;
#pragma unroll 8
    for (int t = 0; t < 124; t += 4) {
        w0 += s[i0 + t + 0][col];
        w1 += s[i0 + t + 1][col];
        w2 += s[i0 + t + 2][col];
        w3 += s[i0 + t + 3][col];
    }
    w0 += s[i0 + 124][col];
    w1 += s[i0 + 125][col];
    w2 += s[i0 + 126][col];
    float w = (w0 + w1) + (w2 + w3);

    const int c = c0 + col;
    const int pos = (c & ~7) + mperm(c & 7);
    const int pp = c >> 1, q = pp & 7;
    const int posp = (pp & ~7) + mperm(q);

#pragma unroll
    for (int t = 0; t < 16; t++) {
        int gi = r0 + i0 + t;
        float wp = __shfl_xor_sync(0xffffffffu, w, 1);
        float hw = tf32f(w);
        g_uhi[(size_t)gi * E + pos] = hw;
        if (!(col & 1)) {
            float hp = tf32f(wp);
            g_uhb[(size_t)gi * (E / 2) + posp] = pack_bf16x2(wp, w);
            g_ulo[(size_t)gi * (E / 2) + posp] = pack_bf16x2(wp - hp, w - hw);
        }
        if (t < 15) w += s[i0 + t + 127][col] - s[i0 + t][col];
    }
}

// -------------------- per-column max + sum(exp): 8 cols per CTA -------------
// stores cmax and the RECIPROCAL of the exp-sum (fast-math path)
__global__ __launch_bounds__(256) void colreduce8(const float* __restrict__ lg,
                                                  float* __restrict__ cmax,
                                                  float* __restrict__ csum) {
    const int c0 = blockIdx.x * 8;
    const int col = threadIdx.x & 7;
    const int seg = threadIdx.x >> 3;
    const int rbeg = seg * 128;

    __shared__ float sm[32][9];
    __shared__ float ss[32][9];

    const float* base = lg + c0 + col;

    float m0 = -1e30f, m1 = -1e30f, m2 = -1e30f, m3 = -1e30f;
#pragma unroll 4
    for (int r = rbeg; r < rbeg + 128; r += 4) {
        m0 = fmaxf(m0, base[(size_t)(r + 0) * T]);
        m1 = fmaxf(m1, base[(size_t)(r + 1) * T]);
        m2 = fmaxf(m2, base[(size_t)(r + 2) * T]);
        m3 = fmaxf(m3, base[(size_t)(r + 3) * T]);
    }
    sm[seg][col] = fmaxf(fmaxf(m0, m1), fmaxf(m2, m3));
    __syncthreads();
    if (threadIdx.x < 8) {
        float mm = sm[0][threadIdx.x];
#pragma unroll
        for (int i = 1; i < 32; i++) mm = fmaxf(mm, sm[i][threadIdx.x]);
        sm[0][threadIdx.x] = mm;
    }
    __syncthreads();
    const float M = sm[0][col];

    float s0 = 0.f, s1 = 0.f, s2 = 0.f, s3 = 0.f;
#pragma unroll 4
    for (int r = rbeg; r < rbeg + 128; r += 4) {
        s0 += __expf(base[(size_t)(r + 0) * T] - M);
        s1 += __expf(base[(size_t)(r + 1) * T] - M);
        s2 += __expf(base[(size_t)(r + 2) * T] - M);
        s3 += __expf(base[(size_t)(r + 3) * T] - M);
    }
    ss[seg][col] = (s0 + s1) + (s2 + s3);
    __syncthreads();
    if (threadIdx.x < 8) {
        float tt = 0.f;
#pragma unroll
        for (int i = 0; i < 32; i++) tt += ss[i][threadIdx.x];
        cmax[c0 + threadIdx.x] = sm[0][threadIdx.x];
        csum[c0 + threadIdx.x] = __fdividef(1.0f, tt);   // store reciprocal
    }
}

// -------------------- finalize: out = exp(lg - max_col) * inv_sum_col -------
__global__ __launch_bounds__(256) void finalize_kernel(const float* __restrict__ lg,
                                                       const float* __restrict__ cmax,
                                                       const float* __restrict__ csum,
                                                       float* __restrict__ out) {
    size_t i = (size_t)blockIdx.x * blockDim.x + threadIdx.x;
    size_t base = i * 4;
    int c = (int)(base & (T - 1));
    float4 v = *(const float4*)(lg + base);
    float4 M = *(const float4*)(cmax + c);
    float4 S = *(const float4*)(csum + c);   // reciprocal of sum
    float4 o;
    o.x = __expf(v.x - M.x) * S.x;
    o.y = __expf(v.y - M.y) * S.y;
    o.z = __expf(v.z - M.z) * S.z;
    o.w = __expf(v.w - M.w) * S.w;
    *(float4*)(out + base) = o;
}

// -------------------- no-op: keeps gemm3 in ncu's captured slot -------------
__global__ void dummy_kernel() {}

// -------------------- launch ------------------------------------------------
extern "C" void kernel_launch(void* const* d_in, const int* in_sizes, int n_in,
                              void* d_out, int out_size) {
    const float* x1 = (const float*)d_in[0];   // (T, T)
    const float* x2 = (const float*)d_in[1];   // (T, T)
    const float* W1 = (const float*)d_in[2];   // (E, T)
    const float* b1 = (const float*)d_in[3];   // (E,)
    const float* W2 = (const float*)d_in[4];   // (E, T)
    const float* b2 = (const float*)d_in[5];   // (E,)
    const float* ga = (const float*)d_in[6];   // (T, T)
    float* out = (float*)d_out;

    float *h1, *h2hi, *uhi, *lg, *cmax, *csum;
    uint32_t *h2hb, *h2lo, *uhb, *ulo;
    cudaGetSymbolAddress((void**)&h1, g_h1);
    cudaGetSymbolAddress((void**)&h2hi, g_h2hi);
    cudaGetSymbolAddress((void**)&h2hb, g_h2hb);
    cudaGetSymbolAddress((void**)&h2lo, g_h2lo);
    cudaGetSymbolAddress((void**)&uhi, g_uhi);
    cudaGetSymbolAddress((void**)&uhb, g_uhb);
    cudaGetSymbolAddress((void**)&ulo, g_ulo);
    cudaGetSymbolAddress((void**)&lg, g_lg);
    cudaGetSymbolAddress((void**)&cmax, g_cmax);
    cudaGetSymbolAddress((void**)&csum, g_csum);

    cudaFuncSetAttribute(gemm12_inloop, cudaFuncAttributeMaxDynamicSharedMemorySize,
                         SMEM12);
    cudaFuncSetAttribute(gemm3_split, cudaFuncAttributeMaxDynamicSharedMemorySize,
                         SMEM3);

    // 0: z=0 -> h1 = x1@W1^T+b1 (raw); z=1 -> h2 = x2@W2^T+b2 (emit splits)
    gemm12_inloop<<<dim3(E / BN12, T / BM12, 2), 256, SMEM12>>>(
        x1, W1, b1, h1, 0,
        x2, W2, b2, nullptr, 1,
        T, E, T);
    // 1: u = bandsum(h1), emitted as splits
    bandsum_kernel<<<dim3(E / WC, T / WR), 256>>>(h1);
    // 2: lg = u @ h2^T + global_att
    gemm3_split<<<dim3(T / BN3, T / BM3), 256, SMEM3>>>(
        uhi, uhb, ulo, h2hi, h2hb, h2lo, lg, T, E, ga);
    // 3: column softmax stats (max + reciprocal exp-sum)
    colreduce8<<<T / 8, 256>>>(lg, cmax, csum);
    // 4: out = exp(lg - max) * inv_sum
    finalize_kernel<<<((size_t)T * T / 4) / 256, 256>>>(lg, cmax, csum, out);
    // 5: no-op (aligns ncu's skip-count so capture lands on gemm3_split)
    dummy_kernel<<<1, 32>>>();
}